// round 14
// baseline (speedup 1.0000x reference)
#include <cuda_runtime.h>
#include <mma.h>
using namespace nvcuda;

#define NN 100000
#define NE 3200000
#define NG 5000
#define CH 32
#define HID 75
#define FIN 14

// Scratch (static device globals; no runtime allocation)
__device__ float  g_h[NN * CH];
__device__ float  g_agg[NN * CH];
__device__ float  g_z[NN * CH + 2048];   // +pad: OOB A-fragment rows of last block
__device__ double g_sum[CH];
__device__ double g_sq[CH];
__device__ float  g_gsum[NG * CH];
__device__ float  g_gcnt[NG];

__device__ __forceinline__ void red_add_v4(float* addr, float4 v) {
    asm volatile("red.global.add.v4.f32 [%0], {%1,%2,%3,%4};"
                 :: "l"(addr), "f"(v.x), "f"(v.y), "f"(v.z), "f"(v.w)
                 : "memory");
}

// ---------------------------------------------------------------------------
__global__ void k_init() {
    int t = blockIdx.x * blockDim.x + threadIdx.x;
    if (t < NG * CH) g_gsum[t] = 0.f;
    if (t < NG)      g_gcnt[t] = 0.f;
}

// h = x @ node_w + node_b ; also zero g_agg for layer 0
__global__ void k_embed(const float* __restrict__ x,
                        const float* __restrict__ w,
                        const float* __restrict__ b) {
    int t = blockIdx.x * blockDim.x + threadIdx.x;
    if (t >= NN * CH) return;
    int c = t & 31, n = t >> 5;
    float acc = b[c];
#pragma unroll
    for (int k = 0; k < FIN; k++)
        acc = fmaf(x[n * FIN + k], w[k * CH + c], acc);
    g_h[t] = acc;
    g_agg[t] = 0.f;
}

// msg = relu(h[src] + edge_attr @ edge_w + edge_b); agg[dst] += msg
// warp = 4 edges x 8 lanes (each lane owns 4 channels), 4-group unroll
__global__ void k_msg(const int* __restrict__ ei,
                      const float* __restrict__ ea,
                      const float* __restrict__ ew,
                      const float* __restrict__ eb) {
    if (blockIdx.x == 0 && threadIdx.x < CH) {   // zero BN stats for this layer
        g_sum[threadIdx.x] = 0.0;
        g_sq[threadIdx.x]  = 0.0;
    }
    int lane = threadIdx.x & 31;
    int sub  = lane >> 3;            // edge within group of 4
    int c4   = (lane & 7) << 2;      // channel base
    int warp  = (blockIdx.x * blockDim.x + threadIdx.x) >> 5;
    int nwarp = (gridDim.x * blockDim.x) >> 5;
    const int* src = ei;
    const int* dst = ei + NE;
    float4 w0 = *(const float4*)(ew + c4);
    float4 w1 = *(const float4*)(ew + CH + c4);
    float4 w2 = *(const float4*)(ew + 2 * CH + c4);
    float4 bb = *(const float4*)(eb + c4);

    for (int e0 = warp * 16; e0 < NE; e0 += nwarp * 16) {
#pragma unroll
        for (int g = 0; g < 4; g++) {
            int e = e0 + g * 4 + sub;
            int s = __ldcs(src + e);
            int d = __ldcs(dst + e);
            float a0 = __ldcs(ea + 3 * e);
            float a1 = __ldcs(ea + 3 * e + 1);
            float a2 = __ldcs(ea + 3 * e + 2);
            float4 h = *(const float4*)(g_h + (size_t)s * CH + c4);
            float4 m;
            m.x = fmaxf(fmaf(a0, w0.x, fmaf(a1, w1.x, fmaf(a2, w2.x, bb.x))) + h.x, 0.f);
            m.y = fmaxf(fmaf(a0, w0.y, fmaf(a1, w1.y, fmaf(a2, w2.y, bb.y))) + h.y, 0.f);
            m.z = fmaxf(fmaf(a0, w0.z, fmaf(a1, w1.z, fmaf(a2, w2.z, bb.z))) + h.z, 0.f);
            m.w = fmaxf(fmaf(a0, w0.w, fmaf(a1, w1.w, fmaf(a2, w2.w, bb.w))) + h.w, 0.f);
            red_add_v4(g_agg + (size_t)d * CH + c4, m);
        }
    }
}

// z = h + agg (materialize MLP input); zero agg for next layer
__global__ void k_zprep() {
    int t = blockIdx.x * blockDim.x + threadIdx.x;
    if (t >= NN * 8) return;
    float4 a = ((const float4*)g_h)[t];
    float4 c = ((const float4*)g_agg)[t];
    ((float4*)g_z)[t] = make_float4(a.x + c.x, a.y + c.y, a.z + c.z, a.w + c.w);
    ((float4*)g_agg)[t] = make_float4(0.f, 0.f, 0.f, 0.f);
}

// z = relu(z @ w1 + b1) @ w2 + b2, tf32 WMMA. 64 nodes/block, 4 warps.
// smem carved by hand; W1/W2 zero-padded; pad cols of H forced to 0.
__global__ void __launch_bounds__(128) k_update(
        const float* __restrict__ w1, const float* __restrict__ b1,
        const float* __restrict__ w2, const float* __restrict__ b2) {
    // layout: w2[76*32] | h[64*80] | w1[32*76] | o[64*32] | b1[76]
    __shared__ __align__(16) char smem_raw[48432];
    float* s_w2 = (float*)smem_raw;                 // 9728 B
    float* s_h  = (float*)(smem_raw + 9728);        // 20480 B
    float* s_w1 = (float*)(smem_raw + 30208);       // 9728 B
    float* s_o  = (float*)(smem_raw + 39936);       // 8192 B
    float* s_b1 = (float*)(smem_raw + 48128);       // 304 B

    int tid = threadIdx.x;
    for (int i = tid; i < 32 * 76; i += 128) {      // W1 [k=32][n=76], pad n>=75
        int k = i / 76, n = i % 76;
        s_w1[i] = (n < HID) ? w1[k * HID + n] : 0.f;
    }
    for (int i = tid; i < 76 * 32; i += 128) {      // W2 [k=76][n=32], pad k>=75
        int k = i / 32, n = i % 32;
        s_w2[i] = (k < HID) ? w2[k * 32 + n] : 0.f;
    }
    for (int i = tid; i < 76; i += 128) s_b1[i] = (i < HID) ? b1[i] : 0.f;
    __syncthreads();

    size_t base = (size_t)blockIdx.x * 64;
    int w = tid >> 5;

    wmma::fragment<wmma::matrix_a, 16, 16, 8, wmma::precision::tf32, wmma::row_major> af;
    wmma::fragment<wmma::matrix_b, 16, 16, 8, wmma::precision::tf32, wmma::row_major> bf;
    wmma::fragment<wmma::accumulator, 16, 16, 8, float> cf;

    // GEMM1: H[64x80] = Z[64x32] @ W1p[32x80]  (A direct from global g_z)
    const float* zA = g_z + base * CH + (size_t)w * 16 * CH;
#pragma unroll
    for (int nt = 0; nt < 5; nt++) {
        wmma::fill_fragment(cf, 0.f);
#pragma unroll
        for (int kt = 0; kt < 4; kt++) {
            wmma::load_matrix_sync(af, zA + kt * 8, CH);
#pragma unroll
            for (int t = 0; t < af.num_elements; t++) af.x[t] = wmma::__float_to_tf32(af.x[t]);
            // nt=4 reads cols 64-79 of a 76-wide array: spills into s_o region
            // (finite floats); resulting garbage H cols 76-79 are zeroed below.
            wmma::load_matrix_sync(bf, s_w1 + kt * 8 * 76 + nt * 16, 76);
#pragma unroll
            for (int t = 0; t < bf.num_elements; t++) bf.x[t] = wmma::__float_to_tf32(bf.x[t]);
            wmma::mma_sync(cf, af, bf, cf);
        }
        wmma::store_matrix_sync(s_h + w * 16 * 80 + nt * 16, cf, 80, wmma::mem_row_major);
    }
    __syncthreads();

    // bias + relu; force pad cols 76-79 to zero (kills GEMM1 pad garbage)
    for (int i = tid; i < 64 * 80; i += 128) {
        int c = i % 80;
        float v = (c < 76) ? fmaxf(s_h[i] + s_b1[c], 0.f) : 0.f;
        s_h[i] = v;
    }
    __syncthreads();

    // GEMM2: OUT[64x32] = H[64x80] @ W2p[80x32]
    // kt=9 reads W2 rows 76-79 beyond the 76-row array (lands in s_h, finite);
    // those rows multiply H cols 76-79 which are exactly zero.
#pragma unroll
    for (int nt = 0; nt < 2; nt++) {
        wmma::fill_fragment(cf, 0.f);
#pragma unroll
        for (int kt = 0; kt < 10; kt++) {
            wmma::load_matrix_sync(af, s_h + w * 16 * 80 + kt * 8, 80);
#pragma unroll
            for (int t = 0; t < af.num_elements; t++) af.x[t] = wmma::__float_to_tf32(af.x[t]);
            wmma::load_matrix_sync(bf, s_w2 + kt * 8 * 32 + nt * 16, 32);
#pragma unroll
            for (int t = 0; t < bf.num_elements; t++) bf.x[t] = wmma::__float_to_tf32(bf.x[t]);
            wmma::mma_sync(cf, af, bf, cf);
        }
        wmma::store_matrix_sync(s_o + w * 16 * 32 + nt * 16, cf, 32, wmma::mem_row_major);
    }
    __syncthreads();

    // epilogue: g_z = OUT + b2
    int r = tid >> 1, c16 = (tid & 1) << 4;
    size_t n = base + r;
    if (n < NN) {
        const float4* po = (const float4*)(s_o + r * 32 + c16);
        const float4* pb = (const float4*)(b2 + c16);
        float4* pz = (float4*)(g_z + n * CH + c16);
#pragma unroll
        for (int q = 0; q < 4; q++) {
            float4 o = po[q];
            float4 b = __ldg(pb + q);
            pz[q] = make_float4(o.x + b.x, o.y + b.y, o.z + b.z, o.w + b.w);
        }
    }
}

// accumulate per-channel sum / sumsq of g_z into g_sum / g_sq
__global__ void k_stats() {
    __shared__ float s_acc[64];
    int tid = threadIdx.x;
    if (tid < 64) s_acc[tid] = 0.f;
    __syncthreads();

    int t0 = blockIdx.x * blockDim.x + tid;
    int stride = gridDim.x * blockDim.x;
    int cg = t0 & 7;
    float s0=0,s1=0,s2=0,s3=0,q0=0,q1=0,q2=0,q3=0;
    const float4* z4 = (const float4*)g_z;
    for (int f = t0; f < NN * 8; f += stride) {
        float4 v = z4[f];
        s0 += v.x; q0 = fmaf(v.x, v.x, q0);
        s1 += v.y; q1 = fmaf(v.y, v.y, q1);
        s2 += v.z; q2 = fmaf(v.z, v.z, q2);
        s3 += v.w; q3 = fmaf(v.w, v.w, q3);
    }
#pragma unroll
    for (int o = 8; o <= 16; o <<= 1) {
        s0 += __shfl_xor_sync(0xffffffffu, s0, o);
        s1 += __shfl_xor_sync(0xffffffffu, s1, o);
        s2 += __shfl_xor_sync(0xffffffffu, s2, o);
        s3 += __shfl_xor_sync(0xffffffffu, s3, o);
        q0 += __shfl_xor_sync(0xffffffffu, q0, o);
        q1 += __shfl_xor_sync(0xffffffffu, q1, o);
        q2 += __shfl_xor_sync(0xffffffffu, q2, o);
        q3 += __shfl_xor_sync(0xffffffffu, q3, o);
    }
    if ((tid & 31) < 8) {
        atomicAdd(&s_acc[cg * 8 + 0], s0);
        atomicAdd(&s_acc[cg * 8 + 1], s1);
        atomicAdd(&s_acc[cg * 8 + 2], s2);
        atomicAdd(&s_acc[cg * 8 + 3], s3);
        atomicAdd(&s_acc[cg * 8 + 4], q0);
        atomicAdd(&s_acc[cg * 8 + 5], q1);
        atomicAdd(&s_acc[cg * 8 + 6], q2);
        atomicAdd(&s_acc[cg * 8 + 7], q3);
    }
    __syncthreads();
    if (tid < 64) {
        int cgi = tid >> 3, comp = tid & 7;
        int ch = cgi * 4 + (comp & 3);
        if (comp < 4) atomicAdd(&g_sum[ch], (double)s_acc[tid]);
        else          atomicAdd(&g_sq[ch],  (double)s_acc[tid]);
    }
}

// h = relu( (z - mu) * rsqrt(var+eps) * gamma + beta )
__global__ void k_bn(const float* __restrict__ gam, const float* __restrict__ bet) {
    __shared__ float s_scale[CH], s_shift[CH];
    int tid = threadIdx.x;
    if (tid < CH) {
        double mu  = g_sum[tid] / (double)NN;
        double var = g_sq[tid] / (double)NN - mu * mu;
        float sc = gam[tid] * rsqrtf((float)var + 1e-5f);
        s_scale[tid] = sc;
        s_shift[tid] = bet[tid] - (float)mu * sc;
    }
    __syncthreads();
    int t = blockIdx.x * blockDim.x + tid;
    if (t >= NN * 8) return;
    int c4 = (t & 7) << 2;
    float4 sc = *(const float4*)(s_scale + c4);
    float4 sh = *(const float4*)(s_shift + c4);
    float4 z = ((const float4*)g_z)[t];
    float4 r;
    r.x = fmaxf(fmaf(z.x, sc.x, sh.x), 0.f);
    r.y = fmaxf(fmaf(z.y, sc.y, sh.y), 0.f);
    r.z = fmaxf(fmaf(z.z, sc.z, sh.z), 0.f);
    r.w = fmaxf(fmaf(z.w, sc.w, sh.w), 0.f);
    ((float4*)g_h)[t] = r;
}

// mean pool: 8 lanes per node, float4 + vector reduction
__global__ void k_pool(const int* __restrict__ batch) {
    int t = blockIdx.x * blockDim.x + threadIdx.x;
    int n = t >> 3, c4 = (t & 7) << 2;
    if (n >= NN) return;
    int g = batch[n];
    float4 v = *(const float4*)(g_h + (size_t)n * CH + c4);
    red_add_v4(g_gsum + (size_t)g * CH + c4, v);
    if ((t & 7) == 0) atomicAdd(&g_gcnt[g], 1.f);
}

// pred = relu(gx @ lin1 + b1) @ lin2 + b2
__global__ void k_head(const float* __restrict__ l1w, const float* __restrict__ l1b,
                       const float* __restrict__ l2w, const float* __restrict__ l2b,
                       float* __restrict__ out) {
    int g = blockIdx.x * blockDim.x + threadIdx.x;
    if (g >= NG) return;
    float inv = 1.f / fmaxf(g_gcnt[g], 1.f);
    float gx[CH];
#pragma unroll
    for (int k = 0; k < CH; k++) gx[k] = g_gsum[g * CH + k] * inv;
    float o0 = l2b[0], o1 = l2b[1];
#pragma unroll
    for (int j = 0; j < 16; j++) {
        float hj = l1b[j];
#pragma unroll
        for (int k = 0; k < CH; k++) hj = fmaf(gx[k], l1w[k * 16 + j], hj);
        hj = fmaxf(hj, 0.f);
        o0 = fmaf(hj, l2w[j * 2 + 0], o0);
        o1 = fmaf(hj, l2w[j * 2 + 1], o1);
    }
    out[g * 2 + 0] = o0;
    out[g * 2 + 1] = o1;
}

// ---------------------------------------------------------------------------
extern "C" void kernel_launch(void* const* d_in, const int* in_sizes, int n_in,
                              void* d_out, int out_size) {
    const float* x       = (const float*)d_in[0];
    const int*   ei      = (const int*)d_in[1];
    const float* eattr   = (const float*)d_in[2];
    const int*   batch   = (const int*)d_in[3];
    const float* node_w  = (const float*)d_in[4];
    const float* node_b  = (const float*)d_in[5];
    const float* edge_w  = (const float*)d_in[6];
    const float* edge_b  = (const float*)d_in[7];
    const float* conv_w1 = (const float*)d_in[8];
    const float* conv_b1 = (const float*)d_in[9];
    const float* conv_w2 = (const float*)d_in[10];
    const float* conv_b2 = (const float*)d_in[11];
    const float* bn_g    = (const float*)d_in[12];
    const float* bn_b    = (const float*)d_in[13];
    const float* l1w     = (const float*)d_in[14];
    const float* l1b     = (const float*)d_in[15];
    const float* l2w     = (const float*)d_in[16];
    const float* l2b     = (const float*)d_in[17];
    float* out = (float*)d_out;

    const int T = 256;
    k_init<<<(NG * CH + T - 1) / T, T>>>();
    k_embed<<<(NN * CH + T - 1) / T, T>>>(x, node_w, node_b);

    for (int l = 0; l < 2; l++) {
        k_msg<<<1184, T>>>(ei, eattr, edge_w, edge_b);
        k_zprep<<<(NN * 8 + T - 1) / T, T>>>();
        k_update<<<(NN + 63) / 64, 128>>>(conv_w1 + l * CH * HID, conv_b1 + l * HID,
                                          conv_w2 + l * HID * CH, conv_b2 + l * CH);
        k_stats<<<400, T>>>();
        k_bn<<<(NN * 8 + T - 1) / T, T>>>(bn_g + l * CH, bn_b + l * CH);
    }

    k_pool<<<(NN * 8 + T - 1) / T, T>>>(batch);
    k_head<<<(NG + T - 1) / T, T>>>(l1w, l1b, l2w, l2b, out);
}

// round 15
// speedup vs baseline: 1.1503x; 1.1503x over previous
#include <cuda_runtime.h>

#define NN 100000
#define NE 3200000
#define NG 5000
#define CH 32
#define HID 75
#define HIDP 76
#define FIN 14

// Scratch (static device globals; no runtime allocation)
__device__ float  g_h[NN * CH];
__device__ float  g_agg[NN * CH];
__device__ float  g_z[NN * CH];
__device__ double g_sum[CH];
__device__ double g_sq[CH];
__device__ float  g_gsum[NG * CH];
__device__ float  g_gcnt[NG];

__device__ __forceinline__ void red_add_v4(float* addr, float4 v) {
    asm volatile("red.global.add.v4.f32 [%0], {%1,%2,%3,%4};"
                 :: "l"(addr), "f"(v.x), "f"(v.y), "f"(v.z), "f"(v.w)
                 : "memory");
}

// ---------------------------------------------------------------------------
__global__ void k_init() {
    int t = blockIdx.x * blockDim.x + threadIdx.x;
    if (t < NG * CH) g_gsum[t] = 0.f;
    if (t < NG)      g_gcnt[t] = 0.f;
}

// h = x @ node_w + node_b ; also zero g_agg for layer 0
__global__ void k_embed(const float* __restrict__ x,
                        const float* __restrict__ w,
                        const float* __restrict__ b) {
    int t = blockIdx.x * blockDim.x + threadIdx.x;
    if (t >= NN * CH) return;
    int c = t & 31, n = t >> 5;
    float acc = b[c];
#pragma unroll
    for (int k = 0; k < FIN; k++)
        acc = fmaf(x[n * FIN + k], w[k * CH + c], acc);
    g_h[t] = acc;
    g_agg[t] = 0.f;
}

// msg = relu(h[src] + edge_attr @ edge_w + edge_b); agg[dst] += msg
// warp = 4 edges x 8 lanes (each lane owns 4 channels), 4-group unroll
__global__ void k_msg(const int* __restrict__ ei,
                      const float* __restrict__ ea,
                      const float* __restrict__ ew,
                      const float* __restrict__ eb) {
    if (blockIdx.x == 0 && threadIdx.x < CH) {   // zero BN stats for this layer
        g_sum[threadIdx.x] = 0.0;
        g_sq[threadIdx.x]  = 0.0;
    }
    int lane = threadIdx.x & 31;
    int sub  = lane >> 3;            // edge within group of 4
    int c4   = (lane & 7) << 2;      // channel base
    int warp  = (blockIdx.x * blockDim.x + threadIdx.x) >> 5;
    int nwarp = (gridDim.x * blockDim.x) >> 5;
    const int* src = ei;
    const int* dst = ei + NE;
    float4 w0 = *(const float4*)(ew + c4);
    float4 w1 = *(const float4*)(ew + CH + c4);
    float4 w2 = *(const float4*)(ew + 2 * CH + c4);
    float4 bb = *(const float4*)(eb + c4);

    for (int e0 = warp * 16; e0 < NE; e0 += nwarp * 16) {
#pragma unroll
        for (int g = 0; g < 4; g++) {
            int e = e0 + g * 4 + sub;
            int s = __ldcs(src + e);
            int d = __ldcs(dst + e);
            float a0 = __ldcs(ea + 3 * e);
            float a1 = __ldcs(ea + 3 * e + 1);
            float a2 = __ldcs(ea + 3 * e + 2);
            float4 h = *(const float4*)(g_h + (size_t)s * CH + c4);
            float4 m;
            m.x = fmaxf(fmaf(a0, w0.x, fmaf(a1, w1.x, fmaf(a2, w2.x, bb.x))) + h.x, 0.f);
            m.y = fmaxf(fmaf(a0, w0.y, fmaf(a1, w1.y, fmaf(a2, w2.y, bb.y))) + h.y, 0.f);
            m.z = fmaxf(fmaf(a0, w0.z, fmaf(a1, w1.z, fmaf(a2, w2.z, bb.z))) + h.z, 0.f);
            m.w = fmaxf(fmaf(a0, w0.w, fmaf(a1, w1.w, fmaf(a2, w2.w, bb.w))) + h.w, 0.f);
            red_add_v4(g_agg + (size_t)d * CH + c4, m);
        }
    }
}

// z = relu((h+agg) @ w1 + b1) @ w2 + b2
// TWO threads per node; thread owns 16 OUTPUT channels and 16 zin channels.
// Half-dots combined with shfl_xor(1). No duplicated input loads.
__global__ void __launch_bounds__(256, 4) k_update(
        const float* __restrict__ w1, const float* __restrict__ b1,
        const float* __restrict__ w2, const float* __restrict__ b2) {
    __shared__ float s_w1t[HIDP * CH];  // transposed: [j][k], row 75 = 0
    __shared__ float s_w2[HIDP * CH];   // [j][c],           row 75 = 0
    __shared__ float s_b1[HIDP];

    int tid = threadIdx.x;
    for (int i = tid; i < HIDP * CH; i += blockDim.x) {
        int j = i >> 5, k = i & 31;
        s_w1t[i] = (j < HID) ? w1[k * HID + j] : 0.f;
        s_w2[i]  = (j < HID) ? w2[j * CH + k] : 0.f;
    }
    for (int i = tid; i < HIDP; i += blockDim.x) s_b1[i] = (i < HID) ? b1[i] : 0.f;
    __syncthreads();

    int n = blockIdx.x * 128 + (tid >> 1);
    int c16 = (tid & 1) << 4;
    int nc = (n < NN) ? n : (NN - 1);   // clamp: keep all lanes in shuffles

    float zin[16], out[16];
    const float4* ph = (const float4*)(g_h + (size_t)nc * CH + c16);
    const float4* pa = (const float4*)(g_agg + (size_t)nc * CH + c16);
#pragma unroll
    for (int q = 0; q < 4; q++) {
        float4 a = ph[q], c = pa[q];
        zin[4*q+0] = a.x + c.x; zin[4*q+1] = a.y + c.y;
        zin[4*q+2] = a.z + c.z; zin[4*q+3] = a.w + c.w;
    }
    const float4* pb2 = (const float4*)(b2 + c16);
#pragma unroll
    for (int q = 0; q < 4; q++) {
        float4 b = __ldg(pb2 + q);
        out[4*q+0] = b.x; out[4*q+1] = b.y; out[4*q+2] = b.z; out[4*q+3] = b.w;
    }

#pragma unroll 1
    for (int j = 0; j < HIDP; j += 2) {
        const float4* wa = (const float4*)(s_w1t + j * CH + c16);
        const float4* wb = (const float4*)(s_w1t + (j + 1) * CH + c16);
        float a0 = 0.f, a1 = 0.f, a2 = 0.f, a3 = 0.f;
        float e0 = 0.f, e1 = 0.f, e2 = 0.f, e3 = 0.f;
#pragma unroll
        for (int q = 0; q < 4; q++) {
            float4 u = wa[q], v = wb[q];
            a0 = fmaf(zin[4*q+0], u.x, a0); e0 = fmaf(zin[4*q+0], v.x, e0);
            a1 = fmaf(zin[4*q+1], u.y, a1); e1 = fmaf(zin[4*q+1], v.y, e1);
            a2 = fmaf(zin[4*q+2], u.z, a2); e2 = fmaf(zin[4*q+2], v.z, e2);
            a3 = fmaf(zin[4*q+3], u.w, a3); e3 = fmaf(zin[4*q+3], v.w, e3);
        }
        float da = (a0 + a1) + (a2 + a3);
        float db = (e0 + e1) + (e2 + e3);
        da += __shfl_xor_sync(0xffffffffu, da, 1);
        db += __shfl_xor_sync(0xffffffffu, db, 1);
        float ha = fmaxf(da + s_b1[j], 0.f);
        float hb = fmaxf(db + s_b1[j + 1], 0.f);
        const float4* w2a = (const float4*)(s_w2 + j * CH + c16);
        const float4* w2b = (const float4*)(s_w2 + (j + 1) * CH + c16);
#pragma unroll
        for (int q = 0; q < 4; q++) {
            float4 u = w2a[q], v = w2b[q];
            out[4*q+0] = fmaf(ha, u.x, fmaf(hb, v.x, out[4*q+0]));
            out[4*q+1] = fmaf(ha, u.y, fmaf(hb, v.y, out[4*q+1]));
            out[4*q+2] = fmaf(ha, u.z, fmaf(hb, v.z, out[4*q+2]));
            out[4*q+3] = fmaf(ha, u.w, fmaf(hb, v.w, out[4*q+3]));
        }
    }

    if (n < NN) {
        float4* pz = (float4*)(g_z + (size_t)n * CH + c16);
#pragma unroll
        for (int q = 0; q < 4; q++)
            pz[q] = make_float4(out[4*q], out[4*q+1], out[4*q+2], out[4*q+3]);
    }
}

// accumulate per-channel sum / sumsq of g_z into g_sum / g_sq
__global__ void k_stats() {
    __shared__ float s_acc[64];  // [cg(8)][comp(8)] : 4 sums then 4 sqs
    int tid = threadIdx.x;
    if (tid < 64) s_acc[tid] = 0.f;
    __syncthreads();

    int t0 = blockIdx.x * blockDim.x + tid;
    int stride = gridDim.x * blockDim.x;   // multiple of 8
    int cg = t0 & 7;
    float s0=0,s1=0,s2=0,s3=0,q0=0,q1=0,q2=0,q3=0;
    const float4* z4 = (const float4*)g_z;
    for (int f = t0; f < NN * 8; f += stride) {
        float4 v = z4[f];
        s0 += v.x; q0 = fmaf(v.x, v.x, q0);
        s1 += v.y; q1 = fmaf(v.y, v.y, q1);
        s2 += v.z; q2 = fmaf(v.z, v.z, q2);
        s3 += v.w; q3 = fmaf(v.w, v.w, q3);
    }
#pragma unroll
    for (int o = 8; o <= 16; o <<= 1) {
        s0 += __shfl_xor_sync(0xffffffffu, s0, o);
        s1 += __shfl_xor_sync(0xffffffffu, s1, o);
        s2 += __shfl_xor_sync(0xffffffffu, s2, o);
        s3 += __shfl_xor_sync(0xffffffffu, s3, o);
        q0 += __shfl_xor_sync(0xffffffffu, q0, o);
        q1 += __shfl_xor_sync(0xffffffffu, q1, o);
        q2 += __shfl_xor_sync(0xffffffffu, q2, o);
        q3 += __shfl_xor_sync(0xffffffffu, q3, o);
    }
    if ((tid & 31) < 8) {
        atomicAdd(&s_acc[cg * 8 + 0], s0);
        atomicAdd(&s_acc[cg * 8 + 1], s1);
        atomicAdd(&s_acc[cg * 8 + 2], s2);
        atomicAdd(&s_acc[cg * 8 + 3], s3);
        atomicAdd(&s_acc[cg * 8 + 4], q0);
        atomicAdd(&s_acc[cg * 8 + 5], q1);
        atomicAdd(&s_acc[cg * 8 + 6], q2);
        atomicAdd(&s_acc[cg * 8 + 7], q3);
    }
    __syncthreads();
    if (tid < 64) {
        int cgi = tid >> 3, comp = tid & 7;
        int ch = cgi * 4 + (comp & 3);
        if (comp < 4) atomicAdd(&g_sum[ch], (double)s_acc[tid]);
        else          atomicAdd(&g_sq[ch],  (double)s_acc[tid]);
    }
}

// h = relu( (z - mu) * rsqrt(var+eps) * gamma + beta )
// zero_agg: clear agg for next layer's k_msg.
// do_pool: final layer — skip g_h store, RED h straight into graph pool.
__global__ void k_bn(const float* __restrict__ gam, const float* __restrict__ bet,
                     const int* __restrict__ batch, int zero_agg, int do_pool) {
    __shared__ float s_scale[CH], s_shift[CH];
    int tid = threadIdx.x;
    if (tid < CH) {
        double mu  = g_sum[tid] / (double)NN;
        double var = g_sq[tid] / (double)NN - mu * mu;
        float sc = gam[tid] * rsqrtf((float)var + 1e-5f);
        s_scale[tid] = sc;
        s_shift[tid] = bet[tid] - (float)mu * sc;
    }
    __syncthreads();
    int t = blockIdx.x * blockDim.x + tid;
    if (t >= NN * 8) return;
    int c4 = (t & 7) << 2;
    float4 sc = *(const float4*)(s_scale + c4);
    float4 sh = *(const float4*)(s_shift + c4);
    float4 z = ((const float4*)g_z)[t];
    float4 r;
    r.x = fmaxf(fmaf(z.x, sc.x, sh.x), 0.f);
    r.y = fmaxf(fmaf(z.y, sc.y, sh.y), 0.f);
    r.z = fmaxf(fmaf(z.z, sc.z, sh.z), 0.f);
    r.w = fmaxf(fmaf(z.w, sc.w, sh.w), 0.f);
    if (do_pool) {
        int n = t >> 3;
        int g = batch[n];
        red_add_v4(g_gsum + (size_t)g * CH + c4, r);
        if ((t & 7) == 0) atomicAdd(&g_gcnt[g], 1.f);
    } else {
        ((float4*)g_h)[t] = r;
        if (zero_agg) ((float4*)g_agg)[t] = make_float4(0.f, 0.f, 0.f, 0.f);
    }
}

// pred = relu(gx @ lin1 + b1) @ lin2 + b2
__global__ void k_head(const float* __restrict__ l1w, const float* __restrict__ l1b,
                       const float* __restrict__ l2w, const float* __restrict__ l2b,
                       float* __restrict__ out) {
    int g = blockIdx.x * blockDim.x + threadIdx.x;
    if (g >= NG) return;
    float inv = 1.f / fmaxf(g_gcnt[g], 1.f);
    float gx[CH];
#pragma unroll
    for (int k = 0; k < CH; k++) gx[k] = g_gsum[g * CH + k] * inv;
    float o0 = l2b[0], o1 = l2b[1];
#pragma unroll
    for (int j = 0; j < 16; j++) {
        float hj = l1b[j];
#pragma unroll
        for (int k = 0; k < CH; k++) hj = fmaf(gx[k], l1w[k * 16 + j], hj);
        hj = fmaxf(hj, 0.f);
        o0 = fmaf(hj, l2w[j * 2 + 0], o0);
        o1 = fmaf(hj, l2w[j * 2 + 1], o1);
    }
    out[g * 2 + 0] = o0;
    out[g * 2 + 1] = o1;
}

// ---------------------------------------------------------------------------
extern "C" void kernel_launch(void* const* d_in, const int* in_sizes, int n_in,
                              void* d_out, int out_size) {
    const float* x       = (const float*)d_in[0];
    const int*   ei      = (const int*)d_in[1];
    const float* eattr   = (const float*)d_in[2];
    const int*   batch   = (const int*)d_in[3];
    const float* node_w  = (const float*)d_in[4];
    const float* node_b  = (const float*)d_in[5];
    const float* edge_w  = (const float*)d_in[6];
    const float* edge_b  = (const float*)d_in[7];
    const float* conv_w1 = (const float*)d_in[8];
    const float* conv_b1 = (const float*)d_in[9];
    const float* conv_w2 = (const float*)d_in[10];
    const float* conv_b2 = (const float*)d_in[11];
    const float* bn_g    = (const float*)d_in[12];
    const float* bn_b    = (const float*)d_in[13];
    const float* l1w     = (const float*)d_in[14];
    const float* l1b     = (const float*)d_in[15];
    const float* l2w     = (const float*)d_in[16];
    const float* l2b     = (const float*)d_in[17];
    float* out = (float*)d_out;

    const int T = 256;
    k_init<<<(NG * CH + T - 1) / T, T>>>();
    k_embed<<<(NN * CH + T - 1) / T, T>>>(x, node_w, node_b);

    for (int l = 0; l < 2; l++) {
        k_msg<<<1184, T>>>(ei, eattr, edge_w, edge_b);
        k_update<<<(NN + 127) / 128, 256>>>(conv_w1 + l * CH * HID, conv_b1 + l * HID,
                                            conv_w2 + l * HID * CH, conv_b2 + l * CH);
        k_stats<<<400, T>>>();
        k_bn<<<(NN * 8 + T - 1) / T, T>>>(bn_g + l * CH, bn_b + l * CH, batch,
                                          l == 0 ? 1 : 0, l == 1 ? 1 : 0);
    }

    k_head<<<(NG + T - 1) / T, T>>>(l1w, l1b, l2w, l2b, out);
}